// round 1
// baseline (speedup 1.0000x reference)
#include <cuda_runtime.h>
#include <math.h>

#define NB 4
#define NN 50000
#define NT (NB*NN)
#define H4 128
#define RF 64
#define CH 196
#define CHSZ 256

#define ALPHA 0.4204482076268573f   /* 32^-0.25 */
#define RATIO 0.125f                /* 1/sqrt(64) */
#define EPSRF 1e-6f
#define EPSLN 1e-5f

/* ------------------------------ scratch ------------------------------ */
__device__ float g_h0[(size_t)NT*H4];
__device__ float g_h [(size_t)NT*H4];
__device__ float g_v [(size_t)NT*H4];
__device__ float g_q [(size_t)NT*RF];
__device__ float g_dash2[(size_t)NT*RF];
__device__ float g_diag2[NT];
__device__ float g_k [(size_t)NT*RF];
__device__ int   g_mx[NB];
__device__ float g_part [(size_t)NB*CH*RF*H4];
__device__ float g_kpart[(size_t)NB*CH*RF];
__device__ float g_v2x[(size_t)NB*RF*H4];
__device__ float g_ksum[NB*RF];

/* ------------------------------ helpers ------------------------------ */
__device__ __forceinline__ float warpSum(float v){
    #pragma unroll
    for (int o=16;o;o>>=1) v += __shfl_xor_sync(0xffffffffu, v, o);
    return v;
}
__device__ __forceinline__ float warpMax(float v){
    #pragma unroll
    for (int o=16;o;o>>=1) v = fmaxf(v, __shfl_xor_sync(0xffffffffu, v, o));
    return v;
}
__device__ __forceinline__ int f2ord(float f){
    int i = __float_as_int(f);
    return (i >= 0) ? i : (i ^ 0x7FFFFFFF);
}
__device__ __forceinline__ float ord2f(int i){
    return __int_as_float((i >= 0) ? i : (i ^ 0x7FFFFFFF));
}

/* ------------------------------ init --------------------------------- */
__global__ void initmx_k(){
    if (threadIdx.x < NB) g_mx[threadIdx.x] = (int)0x80000000;
}

/* --------------------------- phase 1 ---------------------------------
 * Per node: embeddings, input conv, h0/h, q features, dash2/diag2, and
 * deterministic global max of dash2 per batch (ordered-int atomicMax).
 * 1 warp per node, 8 warps / block.
 */
__global__ void phase1_k(const float* __restrict__ x,
                         const float* __restrict__ node_emb,
                         const float* __restrict__ time_emb,
                         const float* __restrict__ week_emb,
                         const float* __restrict__ Win, const float* __restrict__ bin,
                         const float* __restrict__ W1,  const float* __restrict__ b1,
                         const float* __restrict__ W2,  const float* __restrict__ b2,
                         const float* __restrict__ proj)
{
    __shared__ float sWinT[36*32];
    __shared__ float sW1T[96*32];
    __shared__ float sW2T[96*32];
    __shared__ float sprojT[32*64];
    __shared__ float sbin[32], sb1[32], sb2[32];
    __shared__ float swp[8][176];      /* per-warp: xv[36]@0, xg[96]@40, nv[32]@136 */
    __shared__ int   sbmax[NB];

    int tid = threadIdx.x;
    for (int t=tid; t<32*36; t+=256){ int h=t/36, j=t%36; sWinT[j*32+h]=Win[t]; }
    for (int t=tid; t<32*96; t+=256){ int h=t/96, j=t%96; sW1T[j*32+h]=W1[t]; sW2T[j*32+h]=W2[t]; }
    for (int t=tid; t<64*32; t+=256){ int m=t/32, d=t%32; sprojT[d*64+m]=proj[t]; }
    if (tid<32){ sbin[tid]=bin[tid]; sb1[tid]=b1[tid]; sb2[tid]=b2[tid]; }
    if (tid<NB) sbmax[tid] = (int)0x80000000;
    __syncthreads();

    int w = tid>>5, l = tid&31;
    int i = blockIdx.x*8 + w;
    int b = i / NN;
    int n = i - b*NN;

    float* xv = swp[w];
    float* xg = swp[w]+40;
    float* nv = swp[w]+136;

    const float* xr = x + (size_t)i*36;
    xv[l] = xr[l];                 /* lanes 0..31 load 0..31 (only first 32 used below via index) */
    if (l < 4) xv[32+l] = xr[32+l];
    __syncwarp();

    int ti = (int)(xv[34]*288.0f); ti = min(max(ti,0),287);
    int wk = (int)(xv[35]);        wk = min(max(wk,0),6);

    float ne = node_emb[n*32+l];
    float te = time_emb[ti*32+l];
    float we = week_emb[wk*32+l];

    float inp = sbin[l];
    #pragma unroll
    for (int j=0;j<36;j++) inp = fmaf(sWinT[j*32+l], xv[j], inp);

    size_t hb = (size_t)i*128;
    g_h0[hb+l]=inp; g_h0[hb+32+l]=ne; g_h0[hb+64+l]=te; g_h0[hb+96+l]=we;
    g_h [hb+l]=inp; g_h [hb+32+l]=ne; g_h [hb+64+l]=te; g_h [hb+96+l]=we;

    xg[l]=ne; xg[32+l]=te; xg[64+l]=we;
    __syncwarp();

    /* ---- q (per-node max) ---- */
    float a1 = sb1[l];
    #pragma unroll
    for (int j=0;j<96;j++) a1 = fmaf(sW1T[j*32+l], xg[j], a1);
    a1 *= ALPHA;
    nv[l] = a1; __syncwarp();
    float diag1 = 0.5f * warpSum(a1*a1);
    float d0=0.f, d1=0.f;
    #pragma unroll
    for (int dd=0; dd<32; dd++){
        float f = nv[dd];
        d0 = fmaf(f, sprojT[dd*64+l],    d0);
        d1 = fmaf(f, sprojT[dd*64+32+l], d1);
    }
    float mx1 = warpMax(fmaxf(d0,d1));
    g_q[(size_t)i*64 + l]      = RATIO*(expf(d0 - diag1 - mx1) + EPSRF);
    g_q[(size_t)i*64 + 32 + l] = RATIO*(expf(d1 - diag1 - mx1) + EPSRF);
    __syncwarp();

    /* ---- dash2/diag2 (k needs global max) ---- */
    float a2 = sb2[l];
    #pragma unroll
    for (int j=0;j<96;j++) a2 = fmaf(sW2T[j*32+l], xg[j], a2);
    a2 *= ALPHA;
    nv[l] = a2; __syncwarp();
    float diag2 = 0.5f * warpSum(a2*a2);
    d0=0.f; d1=0.f;
    #pragma unroll
    for (int dd=0; dd<32; dd++){
        float f = nv[dd];
        d0 = fmaf(f, sprojT[dd*64+l],    d0);
        d1 = fmaf(f, sprojT[dd*64+32+l], d1);
    }
    g_dash2[(size_t)i*64 + l]      = d0;
    g_dash2[(size_t)i*64 + 32 + l] = d1;
    if (l==0) g_diag2[i] = diag2;
    float mx2 = warpMax(fmaxf(d0,d1));
    if (l==0) atomicMax(&sbmax[b], f2ord(mx2));

    __syncthreads();
    if (tid < NB && sbmax[tid] != (int)0x80000000)
        atomicMax(&g_mx[tid], sbmax[tid]);
}

/* --------------------------- k features ------------------------------ */
__global__ void computek_k(){
    int idx = blockIdx.x*256 + threadIdx.x;   /* grid covers NT*64 exactly */
    int i = idx >> 6;
    int b = i / NN;
    float mx = ord2f(g_mx[b]);
    g_k[idx] = RATIO*(expf(g_dash2[idx] - g_diag2[i] - mx) + EPSRF);
}

/* ------------------------------ GLU ----------------------------------
 * v = sigmoid(h@wiT+bi) * (h@woT+bo).  Weights resident in smem
 * (transposed, conflict-free), 4-node register blocking per warp.
 */
extern __shared__ float dsm[];
__global__ void glu_k(const float* __restrict__ wi, const float* __restrict__ bi,
                      const float* __restrict__ wo, const float* __restrict__ bo)
{
    float* wiT = dsm;               /* 16384 */
    float* woT = dsm + 16384;       /* 16384 */
    float* sbi = dsm + 32768;       /* 128 */
    float* sbo = dsm + 32896;       /* 128 */
    float* hsh = dsm + 33024;       /* 16*512 */

    int tid = threadIdx.x;
    for (int t=tid; t<16384; t+=512){
        int d = t>>7, j = t&127;
        wiT[j*128+d] = wi[t];
        woT[j*128+d] = wo[t];
    }
    if (tid<128){ sbi[tid]=bi[tid]; sbo[tid]=bo[tid]; }
    __syncthreads();

    int w = tid>>5, l = tid&31;
    float* hw = hsh + w*512;
    float4 bi4 = ((float4*)sbi)[l];
    float4 bo4 = ((float4*)sbo)[l];
    int stride = gridDim.x*16*4;

    for (int i0 = (blockIdx.x*16 + w)*4; i0 < NT; i0 += stride){
        const float* src = g_h + (size_t)i0*128;
        #pragma unroll
        for (int c=0;c<16;c++) hw[c*32+l] = src[c*32+l];
        __syncwarp();

        float4 aI[4], aO[4];
        #pragma unroll
        for (int nd=0; nd<4; nd++){ aI[nd]=bi4; aO[nd]=bo4; }

        #pragma unroll 4
        for (int j=0;j<128;j++){
            float4 wi4 = ((float4*)(wiT + j*128))[l];
            float4 wo4 = ((float4*)(woT + j*128))[l];
            #pragma unroll
            for (int nd=0; nd<4; nd++){
                float hj = hw[nd*128 + j];
                aI[nd].x = fmaf(wi4.x, hj, aI[nd].x);
                aI[nd].y = fmaf(wi4.y, hj, aI[nd].y);
                aI[nd].z = fmaf(wi4.z, hj, aI[nd].z);
                aI[nd].w = fmaf(wi4.w, hj, aI[nd].w);
                aO[nd].x = fmaf(wo4.x, hj, aO[nd].x);
                aO[nd].y = fmaf(wo4.y, hj, aO[nd].y);
                aO[nd].z = fmaf(wo4.z, hj, aO[nd].z);
                aO[nd].w = fmaf(wo4.w, hj, aO[nd].w);
            }
        }
        #pragma unroll
        for (int nd=0; nd<4; nd++){
            float4 o;
            o.x = aO[nd].x / (1.f + expf(-aI[nd].x));
            o.y = aO[nd].y / (1.f + expf(-aI[nd].y));
            o.z = aO[nd].z / (1.f + expf(-aI[nd].z));
            o.w = aO[nd].w / (1.f + expf(-aI[nd].w));
            ((float4*)g_v)[(size_t)(i0+nd)*32 + l] = o;
        }
        __syncwarp();
    }
}

/* --------------------- K^T V partial (deterministic) ----------------- */
__global__ void kvred_k(){
    __shared__ float ks[32*64];
    __shared__ float vs[32*128];
    int b = blockIdx.y, ch = blockIdx.x;
    int tid = threadIdx.x, w = tid>>5, l = tid&31;

    float acc[8][4];
    #pragma unroll
    for (int r=0;r<8;r++){ acc[r][0]=0.f; acc[r][1]=0.f; acc[r][2]=0.f; acc[r][3]=0.f; }

    int nb0 = ch*CHSZ;
    for (int t0=0; t0<CHSZ; t0+=32){
        int nb = nb0 + t0;
        for (int t=tid; t<2048; t+=256){
            int nn = t>>6;
            ks[t] = (nb+nn < NN) ? g_k[((size_t)(b*NN+nb))*64 + t] : 0.f;
        }
        for (int t=tid; t<4096; t+=256){
            int nn = t>>7;
            vs[t] = (nb+nn < NN) ? g_v[((size_t)(b*NN+nb))*128 + t] : 0.f;
        }
        __syncthreads();
        for (int nn=0; nn<32; nn++){
            float4 vv = ((float4*)(vs + nn*128))[l];
            #pragma unroll
            for (int r=0;r<8;r++){
                float kv = ks[nn*64 + w*8 + r];
                acc[r][0] = fmaf(kv, vv.x, acc[r][0]);
                acc[r][1] = fmaf(kv, vv.y, acc[r][1]);
                acc[r][2] = fmaf(kv, vv.z, acc[r][2]);
                acc[r][3] = fmaf(kv, vv.w, acc[r][3]);
            }
        }
        __syncthreads();
    }
    size_t pb = (size_t)(b*CH+ch)*64 + w*8;
    #pragma unroll
    for (int r=0;r<8;r++){
        float4 o = make_float4(acc[r][0],acc[r][1],acc[r][2],acc[r][3]);
        ((float4*)g_part)[(pb+r)*32 + l] = o;
    }
}

__global__ void ksump_k(){
    int b = blockIdx.y, ch = blockIdx.x, m = threadIdx.x;  /* 64 threads */
    float s = 0.f;
    int nb = ch*CHSZ;
    for (int nn=0; nn<CHSZ; nn++){
        int n = nb + nn;
        if (n < NN) s += g_k[((size_t)(b*NN+n))*64 + m];
    }
    g_kpart[(size_t)(b*CH+ch)*64 + m] = s;
}

__global__ void vred_k(){
    int idx = blockIdx.x*256 + threadIdx.x;
    if (idx >= NB*64*129) return;
    int b = idx / (64*129);
    int rem = idx - b*64*129;
    int m = rem / 129, d = rem - m*129;
    float s = 0.f;
    if (d < 128){
        for (int ch=0; ch<CH; ch++)
            s += g_part[((size_t)(b*CH+ch)*64 + m)*128 + d];
        g_v2x[((size_t)b*64 + m)*128 + d] = s;
    } else {
        for (int ch=0; ch<CH; ch++)
            s += g_kpart[(size_t)(b*CH+ch)*64 + m];
        g_ksum[b*64 + m] = s;
    }
}

/* ------------- attention out + residual + layernorm ------------------ */
__global__ void attn_k(const float* __restrict__ lg, const float* __restrict__ lb){
    __shared__ float sv2x[64*128];
    __shared__ float sks[64];
    __shared__ float sg[128], sb[128];
    __shared__ float sq[8][256];

    int b = blockIdx.y;
    int tid = threadIdx.x, w = tid>>5, l = tid&31;
    for (int t=tid; t<8192; t+=256) sv2x[t] = g_v2x[(size_t)b*8192 + t];
    if (tid<64)  sks[tid] = g_ksum[b*64 + tid];
    if (tid<128){ sg[tid] = lg[tid]; sb[tid] = lb[tid]; }
    __syncthreads();

    int nb0 = blockIdx.x*32 + w*4;
    float* sqw = sq[w];
    #pragma unroll
    for (int nd=0; nd<4; nd++){
        int n = nb0 + nd;
        if (n < NN){
            size_t i = (size_t)b*NN + n;
            sqw[nd*64 + l]      = g_q[i*64 + l];
            sqw[nd*64 + 32 + l] = g_q[i*64 + 32 + l];
        } else {
            sqw[nd*64 + l] = 0.f; sqw[nd*64 + 32 + l] = 0.f;
        }
    }
    __syncwarp();

    float4 acc[4]; float o2[4];
    #pragma unroll
    for (int nd=0; nd<4; nd++){ acc[nd]=make_float4(0.f,0.f,0.f,0.f); o2[nd]=0.f; }

    for (int m=0; m<64; m++){
        float4 vx = ((float4*)(sv2x + m*128))[l];
        float km = sks[m];
        #pragma unroll
        for (int nd=0; nd<4; nd++){
            float qm = sqw[nd*64 + m];
            acc[nd].x = fmaf(qm, vx.x, acc[nd].x);
            acc[nd].y = fmaf(qm, vx.y, acc[nd].y);
            acc[nd].z = fmaf(qm, vx.z, acc[nd].z);
            acc[nd].w = fmaf(qm, vx.w, acc[nd].w);
            o2[nd]    = fmaf(qm, km, o2[nd]);
        }
    }

    float4 g4 = ((float4*)sg)[l];
    float4 b4 = ((float4*)sb)[l];
    #pragma unroll
    for (int nd=0; nd<4; nd++){
        int n = nb0 + nd;
        if (n >= NN) continue;                 /* warp-uniform branch */
        size_t i = (size_t)b*NN + n;
        float inv = 1.f / o2[nd];
        float4 res = ((float4*)g_h)[i*32 + l];
        float4 t;
        t.x = fmaf(acc[nd].x, inv, res.x);
        t.y = fmaf(acc[nd].y, inv, res.y);
        t.z = fmaf(acc[nd].z, inv, res.z);
        t.w = fmaf(acc[nd].w, inv, res.w);
        float mu = warpSum(t.x+t.y+t.z+t.w) * (1.f/128.f);
        float dx=t.x-mu, dy=t.y-mu, dz=t.z-mu, dw=t.w-mu;
        float var = warpSum(dx*dx+dy*dy+dz*dz+dw*dw) * (1.f/128.f);
        float rs = rsqrtf(var + EPSLN);
        float4 o;
        o.x = dx*rs*g4.x + b4.x;
        o.y = dy*rs*g4.y + b4.y;
        o.z = dz*rs*g4.z + b4.z;
        o.w = dw*rs*g4.w + b4.w;
        ((float4*)g_h)[i*32 + l] = o;
    }
}

/* -------- relu(concat(h0,h)) @ W_reg.T + b_reg, transposed out ------- */
__global__ void final_k(const float* __restrict__ Wreg, const float* __restrict__ breg,
                        float* __restrict__ out)
{
    __shared__ float sWrT[256*12];
    __shared__ float sbr[12];
    int tid = threadIdx.x;
    for (int t=tid; t<3072; t+=256){ int to=t>>8, j=t&255; sWrT[j*12+to] = Wreg[t]; }
    if (tid<12) sbr[tid] = breg[tid];
    __syncthreads();

    int w = tid>>5, l = tid&31;
    int i = blockIdx.x*8 + w;
    int b = i / NN;
    int n = i - b*NN;
    size_t hb = (size_t)i*128;

    float acc[12];
    #pragma unroll
    for (int t=0;t<12;t++) acc[t]=0.f;

    #pragma unroll
    for (int c=0;c<8;c++){
        int j = c*32 + l;
        float vIn = (j < 128) ? g_h0[hb + j] : g_h[hb + j - 128];
        vIn = fmaxf(vIn, 0.f);
        #pragma unroll
        for (int t=0;t<12;t++) acc[t] = fmaf(vIn, sWrT[j*12+t], acc[t]);
    }
    #pragma unroll
    for (int t=0;t<12;t++) acc[t] = warpSum(acc[t]);
    if (l < 12) out[((size_t)b*12 + l)*NN + n] = acc[l] + sbr[l];
}

/* ------------------------------ launch ------------------------------- */
extern "C" void kernel_launch(void* const* d_in, const int* in_sizes, int n_in,
                              void* d_out, int out_size)
{
    const float* x        = (const float*)d_in[0];
    const float* node_emb = (const float*)d_in[1];
    const float* time_emb = (const float*)d_in[2];
    const float* week_emb = (const float*)d_in[3];
    const float* Win      = (const float*)d_in[4];
    const float* bin      = (const float*)d_in[5];
    const float* W1       = (const float*)d_in[6];
    const float* b1       = (const float*)d_in[7];
    const float* W2       = (const float*)d_in[8];
    const float* b2       = (const float*)d_in[9];
    const float* Wreg     = (const float*)d_in[10];
    const float* breg     = (const float*)d_in[11];
    const float* proj     = (const float*)d_in[12];

    const size_t GLU_SMEM = (16384+16384+128+128+16*512)*sizeof(float);  /* 164864 B */
    cudaFuncSetAttribute(glu_k, cudaFuncAttributeMaxDynamicSharedMemorySize, (int)GLU_SMEM);

    initmx_k<<<1,32>>>();
    phase1_k<<<NT/8,256>>>(x, node_emb, time_emb, week_emb,
                           Win, bin, W1, b1, W2, b2, proj);
    computek_k<<<(NT*64)/256,256>>>();

    for (int layer=0; layer<2; layer++){
        const float* wi = (const float*)d_in[13 + layer*6 + 0];
        const float* bi = (const float*)d_in[13 + layer*6 + 1];
        const float* wo = (const float*)d_in[13 + layer*6 + 2];
        const float* bo = (const float*)d_in[13 + layer*6 + 3];
        const float* lg = (const float*)d_in[13 + layer*6 + 4];
        const float* lb = (const float*)d_in[13 + layer*6 + 5];

        glu_k<<<148,512,GLU_SMEM>>>(wi, bi, wo, bo);
        kvred_k<<<dim3(CH,NB),256>>>();
        ksump_k<<<dim3(CH,NB),64>>>();
        vred_k<<<(NB*64*129 + 255)/256,256>>>();
        attn_k<<<dim3((NN+31)/32,NB),256>>>(lg, lb);
    }

    final_k<<<NT/8,256>>>(Wreg, breg, (float*)d_out);
}

// round 3
// speedup vs baseline: 1.2667x; 1.2667x over previous
#include <cuda_runtime.h>
#include <math.h>

#define NB 4
#define NN 50000
#define NT (NB*NN)
#define H4 128
#define RF 64
#define CH 98
#define CHSZ 512

#define ALPHA 0.4204482076268573f   /* 32^-0.25 */
#define RATIO 0.125f                /* 1/sqrt(64) */
#define EPSRF 1e-6f
#define EPSLN 1e-5f

/* ------------------------------ scratch ------------------------------ */
__device__ float g_h0[(size_t)NT*H4];
__device__ float g_h [(size_t)NT*H4];
__device__ float g_v [(size_t)NT*H4];
__device__ float g_q [(size_t)NT*RF];
__device__ float g_dash2[(size_t)NT*RF];
__device__ float g_diag2[NT];
__device__ float g_k [(size_t)NT*RF];
__device__ int   g_mx[NB];
__device__ float g_part [(size_t)NB*CH*RF*H4];
__device__ float g_kpart[(size_t)NB*CH*RF];
__device__ float g_v2x[(size_t)NB*RF*H4];
__device__ float g_ksum[NB*RF];

/* ------------------------------ helpers ------------------------------ */
__device__ __forceinline__ float warpSum(float v){
    #pragma unroll
    for (int o=16;o;o>>=1) v += __shfl_xor_sync(0xffffffffu, v, o);
    return v;
}
__device__ __forceinline__ float warpMax(float v){
    #pragma unroll
    for (int o=16;o;o>>=1) v = fmaxf(v, __shfl_xor_sync(0xffffffffu, v, o));
    return v;
}
__device__ __forceinline__ int f2ord(float f){
    int i = __float_as_int(f);
    return (i >= 0) ? i : (i ^ 0x7FFFFFFF);
}
__device__ __forceinline__ float ord2f(int i){
    return __int_as_float((i >= 0) ? i : (i ^ 0x7FFFFFFF));
}

/* ------------------------------ init --------------------------------- */
__global__ void initmx_k(){
    if (threadIdx.x < NB) g_mx[threadIdx.x] = (int)0x80000000;
}

/* --------------------------- phase 1 ---------------------------------
 * 8 warps/block, each warp processes 8 nodes sequentially (amortize the
 * shared-memory weight fill).  Writes g_h0, g_q, g_dash2, g_diag2, g_mx.
 */
__global__ void phase1_k(const float* __restrict__ x,
                         const float* __restrict__ node_emb,
                         const float* __restrict__ time_emb,
                         const float* __restrict__ week_emb,
                         const float* __restrict__ Win, const float* __restrict__ bin,
                         const float* __restrict__ W1,  const float* __restrict__ b1,
                         const float* __restrict__ W2,  const float* __restrict__ b2,
                         const float* __restrict__ proj)
{
    __shared__ float sWinT[36*32];
    __shared__ float sW1T[96*32];
    __shared__ float sW2T[96*32];
    __shared__ float sprojT[32*64];
    __shared__ float sbin[32], sb1[32], sb2[32];
    __shared__ float swp[8][176];      /* per-warp: xv[36]@0, xg[96]@40, nv[32]@136 */
    __shared__ int   sbmax[NB];

    int tid = threadIdx.x;
    for (int t=tid; t<32*36; t+=256){ int h=t/36, j=t%36; sWinT[j*32+h]=Win[t]; }
    for (int t=tid; t<32*96; t+=256){ int h=t/96, j=t%96; sW1T[j*32+h]=W1[t]; sW2T[j*32+h]=W2[t]; }
    for (int t=tid; t<64*32; t+=256){ int m=t/32, d=t%32; sprojT[d*64+m]=proj[t]; }
    if (tid<32){ sbin[tid]=bin[tid]; sb1[tid]=b1[tid]; sb2[tid]=b2[tid]; }
    if (tid<NB) sbmax[tid] = (int)0x80000000;
    __syncthreads();

    int w = tid>>5, l = tid&31;
    float* xv = swp[w];
    float* xg = swp[w]+40;
    float* nv = swp[w]+136;

    float wmax = -1e30f;

    #pragma unroll 1
    for (int it=0; it<8; it++){
        int i = (blockIdx.x*8 + w)*8 + it;
        int b = i / NN;
        int n = i - b*NN;

        const float* xr = x + (size_t)i*36;
        xv[l] = xr[l];
        if (l < 4) xv[32+l] = xr[32+l];
        __syncwarp();

        int ti = (int)(xv[34]*288.0f); ti = min(max(ti,0),287);
        int wk = (int)(xv[35]);        wk = min(max(wk,0),6);

        float ne = node_emb[n*32+l];
        float te = time_emb[ti*32+l];
        float we = week_emb[wk*32+l];

        float inp = sbin[l];
        #pragma unroll
        for (int j=0;j<36;j++) inp = fmaf(sWinT[j*32+l], xv[j], inp);

        size_t hb = (size_t)i*128;
        g_h0[hb+l]=inp; g_h0[hb+32+l]=ne; g_h0[hb+64+l]=te; g_h0[hb+96+l]=we;

        xg[l]=ne; xg[32+l]=te; xg[64+l]=we;
        __syncwarp();

        /* ---- q (per-node max) ---- */
        float a1 = sb1[l];
        #pragma unroll
        for (int j=0;j<96;j++) a1 = fmaf(sW1T[j*32+l], xg[j], a1);
        a1 *= ALPHA;
        nv[l] = a1; __syncwarp();
        float diag1 = 0.5f * warpSum(a1*a1);
        float d0=0.f, d1=0.f;
        #pragma unroll
        for (int dd=0; dd<32; dd++){
            float f = nv[dd];
            d0 = fmaf(f, sprojT[dd*64+l],    d0);
            d1 = fmaf(f, sprojT[dd*64+32+l], d1);
        }
        float mx1 = warpMax(fmaxf(d0,d1));
        g_q[(size_t)i*64 + l]      = RATIO*(expf(d0 - diag1 - mx1) + EPSRF);
        g_q[(size_t)i*64 + 32 + l] = RATIO*(expf(d1 - diag1 - mx1) + EPSRF);
        __syncwarp();

        /* ---- dash2/diag2 ---- */
        float a2 = sb2[l];
        #pragma unroll
        for (int j=0;j<96;j++) a2 = fmaf(sW2T[j*32+l], xg[j], a2);
        a2 *= ALPHA;
        nv[l] = a2; __syncwarp();
        float diag2 = 0.5f * warpSum(a2*a2);
        d0=0.f; d1=0.f;
        #pragma unroll
        for (int dd=0; dd<32; dd++){
            float f = nv[dd];
            d0 = fmaf(f, sprojT[dd*64+l],    d0);
            d1 = fmaf(f, sprojT[dd*64+32+l], d1);
        }
        g_dash2[(size_t)i*64 + l]      = d0;
        g_dash2[(size_t)i*64 + 32 + l] = d1;
        if (l==0) g_diag2[i] = diag2;
        wmax = fmaxf(wmax, fmaxf(d0,d1));
        __syncwarp();
    }

    {
        /* 50000 % 8 == 0, so all 8 nodes of a warp share one batch. */
        int i0 = (blockIdx.x*8 + w)*8;
        int b = i0 / NN;
        float m = warpMax(wmax);
        if (l==0) atomicMax(&sbmax[b], f2ord(m));
    }

    __syncthreads();
    if (tid < NB && sbmax[tid] != (int)0x80000000)
        atomicMax(&g_mx[tid], sbmax[tid]);
}

/* --------------------------- k features ------------------------------ */
__global__ void computek_k(){
    int idx = blockIdx.x*256 + threadIdx.x;   /* grid covers NT*64 exactly */
    int i = idx >> 6;
    int b = i / NN;
    float mx = ord2f(g_mx[b]);
    g_k[idx] = RATIO*(expf(g_dash2[idx] - g_diag2[i] - mx) + EPSRF);
}

/* ------------------- ksum partial + final (hoisted) ------------------ */
__global__ void ksump_k(){
    __shared__ float red[4][64];
    int b = blockIdx.y, ch = blockIdx.x;
    int tid = threadIdx.x;
    int m = tid & 63, part = tid >> 6;        /* 4 parts x 128 nodes */
    float s = 0.f;
    int nb = ch*CHSZ + part*128;
    #pragma unroll 4
    for (int nn=0; nn<128; nn++){
        int n = nb + nn;
        if (n < NN) s += g_k[((size_t)(b*NN+n))*64 + m];
    }
    red[part][m] = s;
    __syncthreads();
    if (part == 0){
        float t = red[0][m] + red[1][m] + red[2][m] + red[3][m];
        g_kpart[(size_t)(b*CH+ch)*64 + m] = t;
    }
}

__global__ void ksumr_k(){
    int tid = threadIdx.x;          /* 256 = NB*64 */
    int b = tid >> 6, m = tid & 63;
    float s = 0.f;
    for (int ch=0; ch<CH; ch++)
        s += g_kpart[(size_t)(b*CH+ch)*64 + m];
    g_ksum[b*64 + m] = s;
}

/* ------------------------------ GLU ----------------------------------
 * v = sigmoid(h@wiT+bi) * (h@woT+bo).  1024 threads (32 warps), weights
 * resident in smem, 4-node register blocking per warp.
 */
extern __shared__ float dsm[];
__global__ void __launch_bounds__(1024,1)
glu_k(const float* __restrict__ hin,
      const float* __restrict__ wi, const float* __restrict__ bi,
      const float* __restrict__ wo, const float* __restrict__ bo)
{
    float* wiT = dsm;               /* 16384 */
    float* woT = dsm + 16384;       /* 16384 */
    float* sbi = dsm + 32768;       /* 128 */
    float* sbo = dsm + 32896;       /* 128 */
    float* hsh = dsm + 33024;       /* 32*512 */

    int tid = threadIdx.x;
    for (int t=tid; t<16384; t+=1024){
        int d = t>>7, j = t&127;
        wiT[j*128+d] = wi[t];
        woT[j*128+d] = wo[t];
    }
    if (tid<128){ sbi[tid]=bi[tid]; sbo[tid]=bo[tid]; }
    __syncthreads();

    int w = tid>>5, l = tid&31;
    float* hw = hsh + w*512;
    float4 bi4 = ((float4*)sbi)[l];
    float4 bo4 = ((float4*)sbo)[l];
    int stride = gridDim.x*32*4;

    for (int i0 = (blockIdx.x*32 + w)*4; i0 < NT; i0 += stride){
        const float4* src4 = (const float4*)(hin + (size_t)i0*128);
        #pragma unroll
        for (int c=0;c<4;c++) ((float4*)hw)[c*32+l] = src4[c*32+l];
        __syncwarp();

        float4 aI[4], aO[4];
        #pragma unroll
        for (int nd=0; nd<4; nd++){ aI[nd]=bi4; aO[nd]=bo4; }

        #pragma unroll 4
        for (int j=0;j<128;j++){
            float4 wi4 = ((float4*)(wiT + j*128))[l];
            float4 wo4 = ((float4*)(woT + j*128))[l];
            #pragma unroll
            for (int nd=0; nd<4; nd++){
                float hj = hw[nd*128 + j];
                aI[nd].x = fmaf(wi4.x, hj, aI[nd].x);
                aI[nd].y = fmaf(wi4.y, hj, aI[nd].y);
                aI[nd].z = fmaf(wi4.z, hj, aI[nd].z);
                aI[nd].w = fmaf(wi4.w, hj, aI[nd].w);
                aO[nd].x = fmaf(wo4.x, hj, aO[nd].x);
                aO[nd].y = fmaf(wo4.y, hj, aO[nd].y);
                aO[nd].z = fmaf(wo4.z, hj, aO[nd].z);
                aO[nd].w = fmaf(wo4.w, hj, aO[nd].w);
            }
        }
        #pragma unroll
        for (int nd=0; nd<4; nd++){
            float4 o;
            o.x = aO[nd].x / (1.f + expf(-aI[nd].x));
            o.y = aO[nd].y / (1.f + expf(-aI[nd].y));
            o.z = aO[nd].z / (1.f + expf(-aI[nd].z));
            o.w = aO[nd].w / (1.f + expf(-aI[nd].w));
            ((float4*)g_v)[(size_t)(i0+nd)*32 + l] = o;
        }
        __syncwarp();
    }
}

/* --------------------- K^T V partial (deterministic) ----------------- */
__global__ void kvred_k(){
    __shared__ float ks[32*64];
    __shared__ float vs[32*128];
    int b = blockIdx.y, ch = blockIdx.x;
    int tid = threadIdx.x, w = tid>>5, l = tid&31;

    float acc[8][4];
    #pragma unroll
    for (int r=0;r<8;r++){ acc[r][0]=0.f; acc[r][1]=0.f; acc[r][2]=0.f; acc[r][3]=0.f; }

    int nb0 = ch*CHSZ;
    for (int t0=0; t0<CHSZ; t0+=32){
        int nb = nb0 + t0;
        for (int t=tid; t<2048; t+=256){
            int nn = t>>6;
            ks[t] = (nb+nn < NN) ? g_k[((size_t)(b*NN+nb))*64 + t] : 0.f;
        }
        for (int t=tid; t<4096; t+=256){
            int nn = t>>7;
            vs[t] = (nb+nn < NN) ? g_v[((size_t)(b*NN+nb))*128 + t] : 0.f;
        }
        __syncthreads();
        for (int nn=0; nn<32; nn++){
            float4 vv = ((float4*)(vs + nn*128))[l];
            #pragma unroll
            for (int r=0;r<8;r++){
                float kv = ks[nn*64 + w*8 + r];
                acc[r][0] = fmaf(kv, vv.x, acc[r][0]);
                acc[r][1] = fmaf(kv, vv.y, acc[r][1]);
                acc[r][2] = fmaf(kv, vv.z, acc[r][2]);
                acc[r][3] = fmaf(kv, vv.w, acc[r][3]);
            }
        }
        __syncthreads();
    }
    size_t pb = (size_t)(b*CH+ch)*64 + w*8;
    #pragma unroll
    for (int r=0;r<8;r++){
        float4 o = make_float4(acc[r][0],acc[r][1],acc[r][2],acc[r][3]);
        ((float4*)g_part)[(pb+r)*32 + l] = o;
    }
}

__global__ void vred_k(){
    int idx = blockIdx.x*256 + threadIdx.x;   /* NB*64*128 = 32768 exact */
    int b = idx >> 13;
    int rem = idx & 8191;
    int m = rem >> 7, d = rem & 127;
    float s = 0.f;
    for (int ch=0; ch<CH; ch++)
        s += g_part[((size_t)(b*CH+ch)*64 + m)*128 + d];
    g_v2x[((size_t)b*64 + m)*128 + d] = s;
}

/* ------------- attention out + residual + layernorm ------------------
 * q kept in registers (2 per node per lane); broadcast via shfl in the
 * m-loop.  No sq staging -> static smem fits, 64 nodes/block retained.
 */
__global__ void attn_k(const float* __restrict__ res_in,
                       const float* __restrict__ lg, const float* __restrict__ lb){
    __shared__ float sv2x[64*128];
    __shared__ float sks[64];
    __shared__ float sg[128], sb[128];

    int b = blockIdx.y;
    int tid = threadIdx.x, w = tid>>5, l = tid&31;
    for (int t=tid; t<8192; t+=256) sv2x[t] = g_v2x[(size_t)b*8192 + t];
    if (tid<64)  sks[tid] = g_ksum[b*64 + tid];
    if (tid<128){ sg[tid] = lg[tid]; sb[tid] = lb[tid]; }
    __syncthreads();

    int nb0 = (blockIdx.x*8 + w)*8;
    float q0[8], q1[8];
    #pragma unroll
    for (int nd=0; nd<8; nd++){
        int n = nb0 + nd;
        if (n < NN){
            size_t i = (size_t)b*NN + n;
            q0[nd] = g_q[i*64 + l];
            q1[nd] = g_q[i*64 + 32 + l];
        } else { q0[nd] = 0.f; q1[nd] = 0.f; }
    }

    float4 acc[8]; float o2[8];
    #pragma unroll
    for (int nd=0; nd<8; nd++){ acc[nd]=make_float4(0.f,0.f,0.f,0.f); o2[nd]=0.f; }

    #pragma unroll 4
    for (int m=0; m<32; m++){
        float4 vx = ((float4*)(sv2x + m*128))[l];
        float km = sks[m];
        #pragma unroll
        for (int nd=0; nd<8; nd++){
            float qm = __shfl_sync(0xffffffffu, q0[nd], m);
            acc[nd].x = fmaf(qm, vx.x, acc[nd].x);
            acc[nd].y = fmaf(qm, vx.y, acc[nd].y);
            acc[nd].z = fmaf(qm, vx.z, acc[nd].z);
            acc[nd].w = fmaf(qm, vx.w, acc[nd].w);
            o2[nd]    = fmaf(qm, km, o2[nd]);
        }
    }
    #pragma unroll 4
    for (int m=0; m<32; m++){
        float4 vx = ((float4*)(sv2x + (m+32)*128))[l];
        float km = sks[m+32];
        #pragma unroll
        for (int nd=0; nd<8; nd++){
            float qm = __shfl_sync(0xffffffffu, q1[nd], m);
            acc[nd].x = fmaf(qm, vx.x, acc[nd].x);
            acc[nd].y = fmaf(qm, vx.y, acc[nd].y);
            acc[nd].z = fmaf(qm, vx.z, acc[nd].z);
            acc[nd].w = fmaf(qm, vx.w, acc[nd].w);
            o2[nd]    = fmaf(qm, km, o2[nd]);
        }
    }

    float4 g4 = ((float4*)sg)[l];
    float4 b4 = ((float4*)sb)[l];
    #pragma unroll 1
    for (int nd=0; nd<8; nd++){
        int n = nb0 + nd;
        if (n >= NN) continue;                 /* warp-uniform branch */
        size_t i = (size_t)b*NN + n;
        float inv = 1.f / o2[nd];
        float4 res = ((const float4*)res_in)[i*32 + l];
        float4 t;
        t.x = fmaf(acc[nd].x, inv, res.x);
        t.y = fmaf(acc[nd].y, inv, res.y);
        t.z = fmaf(acc[nd].z, inv, res.z);
        t.w = fmaf(acc[nd].w, inv, res.w);
        float mu = warpSum(t.x+t.y+t.z+t.w) * (1.f/128.f);
        float dx=t.x-mu, dy=t.y-mu, dz=t.z-mu, dw=t.w-mu;
        float var = warpSum(dx*dx+dy*dy+dz*dz+dw*dw) * (1.f/128.f);
        float rs = rsqrtf(var + EPSLN);
        float4 o;
        o.x = dx*rs*g4.x + b4.x;
        o.y = dy*rs*g4.y + b4.y;
        o.z = dz*rs*g4.z + b4.z;
        o.w = dw*rs*g4.w + b4.w;
        ((float4*)g_h)[i*32 + l] = o;
    }
}

/* -------- relu(concat(h0,h)) @ W_reg.T + b_reg, transposed out ------- */
__global__ void final_k(const float* __restrict__ Wreg, const float* __restrict__ breg,
                        float* __restrict__ out)
{
    __shared__ float sWrT[256*12];
    __shared__ float sbr[12];
    int tid = threadIdx.x;
    for (int t=tid; t<3072; t+=256){ int to=t>>8, j=t&255; sWrT[j*12+to] = Wreg[t]; }
    if (tid<12) sbr[tid] = breg[tid];
    __syncthreads();

    int w = tid>>5, l = tid&31;
    int i = blockIdx.x*8 + w;
    int b = i / NN;
    int n = i - b*NN;
    size_t hb = (size_t)i*128;

    float acc[12];
    #pragma unroll
    for (int t=0;t<12;t++) acc[t]=0.f;

    #pragma unroll
    for (int c=0;c<8;c++){
        int j = c*32 + l;
        float vIn = (j < 128) ? g_h0[hb + j] : g_h[hb + j - 128];
        vIn = fmaxf(vIn, 0.f);
        #pragma unroll
        for (int t=0;t<12;t++) acc[t] = fmaf(vIn, sWrT[j*12+t], acc[t]);
    }
    #pragma unroll
    for (int t=0;t<12;t++) acc[t] = warpSum(acc[t]);
    if (l < 12) out[((size_t)b*12 + l)*NN + n] = acc[l] + sbr[l];
}

/* ------------------------------ launch ------------------------------- */
extern "C" void kernel_launch(void* const* d_in, const int* in_sizes, int n_in,
                              void* d_out, int out_size)
{
    const float* x        = (const float*)d_in[0];
    const float* node_emb = (const float*)d_in[1];
    const float* time_emb = (const float*)d_in[2];
    const float* week_emb = (const float*)d_in[3];
    const float* Win      = (const float*)d_in[4];
    const float* bin      = (const float*)d_in[5];
    const float* W1       = (const float*)d_in[6];
    const float* b1       = (const float*)d_in[7];
    const float* W2       = (const float*)d_in[8];
    const float* b2       = (const float*)d_in[9];
    const float* Wreg     = (const float*)d_in[10];
    const float* breg     = (const float*)d_in[11];
    const float* proj     = (const float*)d_in[12];

    const size_t GLU_SMEM = (16384+16384+128+128+32*512)*sizeof(float);  /* 197632 B */
    cudaFuncSetAttribute(glu_k, cudaFuncAttributeMaxDynamicSharedMemorySize, (int)GLU_SMEM);

    float* g_h_ptr;  cudaGetSymbolAddress((void**)&g_h_ptr,  g_h);
    float* g_h0_ptr; cudaGetSymbolAddress((void**)&g_h0_ptr, g_h0);

    initmx_k<<<1,32>>>();
    phase1_k<<<NT/64,256>>>(x, node_emb, time_emb, week_emb,
                            Win, bin, W1, b1, W2, b2, proj);
    computek_k<<<(NT*64)/256,256>>>();
    ksump_k<<<dim3(CH,NB),256>>>();
    ksumr_k<<<1,256>>>();

    for (int layer=0; layer<2; layer++){
        const float* wi = (const float*)d_in[13 + layer*6 + 0];
        const float* bi = (const float*)d_in[13 + layer*6 + 1];
        const float* wo = (const float*)d_in[13 + layer*6 + 2];
        const float* bo = (const float*)d_in[13 + layer*6 + 3];
        const float* lg = (const float*)d_in[13 + layer*6 + 4];
        const float* lb = (const float*)d_in[13 + layer*6 + 5];

        const float* hin = (layer == 0) ? g_h0_ptr : g_h_ptr;

        glu_k<<<148,1024,GLU_SMEM>>>(hin, wi, bi, wo, bo);
        kvred_k<<<dim3(CH,NB),256>>>();
        vred_k<<<128,256>>>();
        attn_k<<<dim3((NN+63)/64,NB),256>>>(hin, lg, lb);
    }

    final_k<<<NT/8,256>>>(Wreg, breg, (float*)d_out);
}

// round 5
// speedup vs baseline: 1.7001x; 1.3421x over previous
#include <cuda_runtime.h>
#include <cuda_bf16.h>
#include <math.h>
#include <stdint.h>

#define NB 4
#define NN 50000
#define NT (NB*NN)
#define H4 128
#define RF 64
#define CH 98
#define CHSZ 512

#define ALPHA 0.4204482076268573f   /* 32^-0.25 */
#define RATIO 0.125f                /* 1/sqrt(64) */
#define EPSRF 1e-6f
#define EPSLN 1e-5f

/* ------------------------------ scratch ------------------------------ */
__device__ float g_h0[(size_t)NT*H4];
__device__ float g_h [(size_t)NT*H4];
__device__ float g_v [(size_t)NT*H4];
__device__ float g_q [(size_t)NT*RF];
__device__ float g_dash2[(size_t)NT*RF];
__device__ float g_diag2[NT];
__device__ float g_k [(size_t)NT*RF];
__device__ int   g_mx[NB];
__device__ float g_part [(size_t)NB*CH*RF*H4];
__device__ float g_kpart[(size_t)NB*CH*RF];
__device__ float g_v2x[(size_t)NB*RF*H4];
__device__ float g_ksum[NB*RF];

/* ------------------------------ helpers ------------------------------ */
__device__ __forceinline__ float warpSum(float v){
    #pragma unroll
    for (int o=16;o;o>>=1) v += __shfl_xor_sync(0xffffffffu, v, o);
    return v;
}
__device__ __forceinline__ float warpMax(float v){
    #pragma unroll
    for (int o=16;o;o>>=1) v = fmaxf(v, __shfl_xor_sync(0xffffffffu, v, o));
    return v;
}
__device__ __forceinline__ int f2ord(float f){
    int i = __float_as_int(f);
    return (i >= 0) ? i : (i ^ 0x7FFFFFFF);
}
__device__ __forceinline__ float ord2f(int i){
    return __int_as_float((i >= 0) ? i : (i ^ 0x7FFFFFFF));
}

/* --------------------- mma.sync helpers (base sm_100 ISA) ------------ */
__device__ __forceinline__ uint32_t smem_u32(const void* p){
    uint32_t a;
    asm("{ .reg .u64 t; cvta.to.shared.u64 t, %1; cvt.u32.u64 %0, t; }"
        : "=r"(a) : "l"(p));
    return a;
}
__device__ __forceinline__ void ldsm_x4(uint32_t* r, uint32_t addr){
    asm volatile("ldmatrix.sync.aligned.m8n8.x4.shared.b16 {%0,%1,%2,%3}, [%4];"
        : "=r"(r[0]), "=r"(r[1]), "=r"(r[2]), "=r"(r[3]) : "r"(addr));
}
__device__ __forceinline__ void mma16816(float* d, const uint32_t* a, const uint32_t* b){
    asm volatile("mma.sync.aligned.m16n8k16.row.col.f32.bf16.bf16.f32 "
        "{%0,%1,%2,%3}, {%4,%5,%6,%7}, {%8,%9}, {%0,%1,%2,%3};"
        : "+f"(d[0]), "+f"(d[1]), "+f"(d[2]), "+f"(d[3])
        : "r"(a[0]), "r"(a[1]), "r"(a[2]), "r"(a[3]), "r"(b[0]), "r"(b[1]));
}
__device__ __forceinline__ uint4 pack8_bf16(const float* src){
    float4 a = ((const float4*)src)[0];
    float4 b = ((const float4*)src)[1];
    __nv_bfloat162 p0 = __floats2bfloat162_rn(a.x, a.y);
    __nv_bfloat162 p1 = __floats2bfloat162_rn(a.z, a.w);
    __nv_bfloat162 p2 = __floats2bfloat162_rn(b.x, b.y);
    __nv_bfloat162 p3 = __floats2bfloat162_rn(b.z, b.w);
    uint4 w;
    w.x = *reinterpret_cast<uint32_t*>(&p0);
    w.y = *reinterpret_cast<uint32_t*>(&p1);
    w.z = *reinterpret_cast<uint32_t*>(&p2);
    w.w = *reinterpret_cast<uint32_t*>(&p3);
    return w;
}

/* ------------------------------ init --------------------------------- */
__global__ void initmx_k(){
    if (threadIdx.x < NB) g_mx[threadIdx.x] = (int)0x80000000;
}

/* --------------------------- phase 1 --------------------------------- */
__global__ void phase1_k(const float* __restrict__ x,
                         const float* __restrict__ node_emb,
                         const float* __restrict__ time_emb,
                         const float* __restrict__ week_emb,
                         const float* __restrict__ Win, const float* __restrict__ bin,
                         const float* __restrict__ W1,  const float* __restrict__ b1,
                         const float* __restrict__ W2,  const float* __restrict__ b2,
                         const float* __restrict__ proj)
{
    __shared__ float sWinT[36*32];
    __shared__ float sW1T[96*32];
    __shared__ float sW2T[96*32];
    __shared__ float sprojT[32*64];
    __shared__ float sbin[32], sb1[32], sb2[32];
    __shared__ float swp[8][176];
    __shared__ int   sbmax[NB];

    int tid = threadIdx.x;
    for (int t=tid; t<32*36; t+=256){ int h=t/36, j=t%36; sWinT[j*32+h]=Win[t]; }
    for (int t=tid; t<32*96; t+=256){ int h=t/96, j=t%96; sW1T[j*32+h]=W1[t]; sW2T[j*32+h]=W2[t]; }
    for (int t=tid; t<64*32; t+=256){ int m=t/32, d=t%32; sprojT[d*64+m]=proj[t]; }
    if (tid<32){ sbin[tid]=bin[tid]; sb1[tid]=b1[tid]; sb2[tid]=b2[tid]; }
    if (tid<NB) sbmax[tid] = (int)0x80000000;
    __syncthreads();

    int w = tid>>5, l = tid&31;
    float* xv = swp[w];
    float* xg = swp[w]+40;
    float* nv = swp[w]+136;

    float wmax = -1e30f;

    #pragma unroll 1
    for (int it=0; it<8; it++){
        int i = (blockIdx.x*8 + w)*8 + it;
        int b = i / NN;
        int n = i - b*NN;

        const float* xr = x + (size_t)i*36;
        xv[l] = xr[l];
        if (l < 4) xv[32+l] = xr[32+l];
        __syncwarp();

        int ti = (int)(xv[34]*288.0f); ti = min(max(ti,0),287);
        int wk = (int)(xv[35]);        wk = min(max(wk,0),6);

        float ne = node_emb[n*32+l];
        float te = time_emb[ti*32+l];
        float we = week_emb[wk*32+l];

        float inp = sbin[l];
        #pragma unroll
        for (int j=0;j<36;j++) inp = fmaf(sWinT[j*32+l], xv[j], inp);

        size_t hb = (size_t)i*128;
        g_h0[hb+l]=inp; g_h0[hb+32+l]=ne; g_h0[hb+64+l]=te; g_h0[hb+96+l]=we;

        xg[l]=ne; xg[32+l]=te; xg[64+l]=we;
        __syncwarp();

        float a1 = sb1[l];
        #pragma unroll
        for (int j=0;j<96;j++) a1 = fmaf(sW1T[j*32+l], xg[j], a1);
        a1 *= ALPHA;
        nv[l] = a1; __syncwarp();
        float diag1 = 0.5f * warpSum(a1*a1);
        float d0=0.f, d1=0.f;
        #pragma unroll
        for (int dd=0; dd<32; dd++){
            float f = nv[dd];
            d0 = fmaf(f, sprojT[dd*64+l],    d0);
            d1 = fmaf(f, sprojT[dd*64+32+l], d1);
        }
        float mx1 = warpMax(fmaxf(d0,d1));
        g_q[(size_t)i*64 + l]      = RATIO*(expf(d0 - diag1 - mx1) + EPSRF);
        g_q[(size_t)i*64 + 32 + l] = RATIO*(expf(d1 - diag1 - mx1) + EPSRF);
        __syncwarp();

        float a2 = sb2[l];
        #pragma unroll
        for (int j=0;j<96;j++) a2 = fmaf(sW2T[j*32+l], xg[j], a2);
        a2 *= ALPHA;
        nv[l] = a2; __syncwarp();
        float diag2 = 0.5f * warpSum(a2*a2);
        d0=0.f; d1=0.f;
        #pragma unroll
        for (int dd=0; dd<32; dd++){
            float f = nv[dd];
            d0 = fmaf(f, sprojT[dd*64+l],    d0);
            d1 = fmaf(f, sprojT[dd*64+32+l], d1);
        }
        g_dash2[(size_t)i*64 + l]      = d0;
        g_dash2[(size_t)i*64 + 32 + l] = d1;
        if (l==0) g_diag2[i] = diag2;
        wmax = fmaxf(wmax, fmaxf(d0,d1));
        __syncwarp();
    }

    {
        int i0 = (blockIdx.x*8 + w)*8;
        int b = i0 / NN;
        float m = warpMax(wmax);
        if (l==0) atomicMax(&sbmax[b], f2ord(m));
    }

    __syncthreads();
    if (tid < NB && sbmax[tid] != (int)0x80000000)
        atomicMax(&g_mx[tid], sbmax[tid]);
}

/* --------------------------- k features ------------------------------ */
__global__ void computek_k(){
    int idx = blockIdx.x*256 + threadIdx.x;
    int i = idx >> 6;
    int b = i / NN;
    float mx = ord2f(g_mx[b]);
    g_k[idx] = RATIO*(expf(g_dash2[idx] - g_diag2[i] - mx) + EPSRF);
}

/* ------------------- ksum partial + final (hoisted) ------------------ */
__global__ void ksump_k(){
    __shared__ float red[4][64];
    int b = blockIdx.y, ch = blockIdx.x;
    int tid = threadIdx.x;
    int m = tid & 63, part = tid >> 6;
    float s = 0.f;
    int nb = ch*CHSZ + part*128;
    #pragma unroll 4
    for (int nn=0; nn<128; nn++){
        int n = nb + nn;
        if (n < NN) s += g_k[((size_t)(b*NN+n))*64 + m];
    }
    red[part][m] = s;
    __syncthreads();
    if (part == 0){
        float t = red[0][m] + red[1][m] + red[2][m] + red[3][m];
        g_kpart[(size_t)(b*CH+ch)*64 + m] = t;
    }
}

__global__ void ksumr_k(){
    int tid = threadIdx.x;
    int b = tid >> 6, m = tid & 63;
    float s = 0.f;
    for (int ch=0; ch<CH; ch++)
        s += g_kpart[(size_t)(b*CH+ch)*64 + m];
    g_ksum[b*64 + m] = s;
}

/* ------------------------- GLU via mma.sync --------------------------
 * Per block: tile of 256 nodes.  D[256x256] = A[256x128]_bf16 . W^T,
 * W = [wi;wo] (256x128) staged once as bf16.  512 thr = 16 warps, warp w
 * owns rows 16w..16w+15.  XOR-swizzled 16B chunks; ldmatrix conflict-free.
 * Epilogue: v = (aO+bo) * sigmoid(aI+bi), float2 stores.
 */
#define GT_TILES ((NT + 255)/256)
#define G3_SA   0
#define G3_SB   65536
#define G3_SBI  131072
#define G3_SBO  131584
#define G3_TOT  132096

extern __shared__ char gsm2[];

__global__ void __launch_bounds__(512,1)
glu3_k(const float* __restrict__ hin,
       const float* __restrict__ wi, const float* __restrict__ bi,
       const float* __restrict__ wo, const float* __restrict__ bo)
{
    char* SA = gsm2 + G3_SA;
    char* SB = gsm2 + G3_SB;
    float* sbi = (float*)(gsm2 + G3_SBI);
    float* sbo = (float*)(gsm2 + G3_SBO);
    int tid = threadIdx.x;

    /* stage W = [wi(128); wo(128)] as bf16, swizzled 16B chunks */
    for (int c = tid; c < 4096; c += 512){
        int n = c >> 4, ch = c & 15;
        const float* src = (n < 128) ? (wi + (size_t)n*128 + ch*8)
                                     : (wo + (size_t)(n-128)*128 + ch*8);
        *reinterpret_cast<uint4*>(SB + n*256 + ((ch ^ (n&7))<<4)) = pack8_bf16(src);
    }
    if (tid < 128){ sbi[tid] = bi[tid]; sbo[tid] = bo[tid]; }

    int w = tid>>5, l = tid&31;
    uint32_t saB = smem_u32(SA);
    uint32_t sbB = smem_u32(SB);

    int a_row = (w<<4) + (l & 15);            /* ldmatrix A row for this lane */
    int er    = (w<<4) + (l>>2);              /* epilogue row (and +8) */

    for (int tile = blockIdx.x; tile < GT_TILES; tile += gridDim.x){
        int base = tile << 8;

        /* stage A tile (256 x 128 fp32 -> bf16, swizzled) */
        for (int c = tid; c < 4096; c += 512){
            int r = c >> 4, ch = c & 15;
            uint4 pw = make_uint4(0,0,0,0);
            if (base + r < NT)
                pw = pack8_bf16(hin + (size_t)(base + r)*128 + ch*8);
            *reinterpret_cast<uint4*>(SA + r*256 + ((ch ^ (r&7))<<4)) = pw;
        }
        __syncthreads();

        /* preload all 8 A k-step fragments */
        uint32_t Af[8][4];
        #pragma unroll
        for (int ks=0; ks<8; ks++){
            int kc = (ks<<1) + (l>>4);
            ldsm_x4(Af[ks], saB + a_row*256 + ((kc ^ (a_row&7))<<4));
        }

        #pragma unroll 1
        for (int nb=0; nb<16; nb++){
            int nrI = (nb<<3) + (l&7);
            int nrO = nrI + 128;
            uint32_t BI[16], BO[16];
            #pragma unroll
            for (int j=0;j<4;j++){
                int kc = (j<<2) + (l>>3);
                ldsm_x4(&BI[j<<2], sbB + nrI*256 + ((kc ^ (nrI&7))<<4));
                ldsm_x4(&BO[j<<2], sbB + nrO*256 + ((kc ^ (nrO&7))<<4));
            }
            float dI[4] = {0.f,0.f,0.f,0.f};
            float dO[4] = {0.f,0.f,0.f,0.f};
            #pragma unroll
            for (int ks=0; ks<8; ks++){
                mma16816(dI, Af[ks], &BI[ks<<1]);
                mma16816(dO, Af[ks], &BO[ks<<1]);
            }

            int c0 = (nb<<3) + ((l&3)<<1);
            float bi0 = sbi[c0], bi1 = sbi[c0+1];
            float bo0 = sbo[c0], bo1 = sbo[c0+1];
            int n0 = base + er;
            int n1 = n0 + 8;
            if (n0 < NT){
                float aI0 = dI[0] + bi0, aI1 = dI[1] + bi1;
                float2 o;
                o.x = (dO[0] + bo0) / (1.f + expf(-aI0));
                o.y = (dO[1] + bo1) / (1.f + expf(-aI1));
                *reinterpret_cast<float2*>(g_v + (size_t)n0*128 + c0) = o;
            }
            if (n1 < NT){
                float aI2 = dI[2] + bi0, aI3 = dI[3] + bi1;
                float2 o;
                o.x = (dO[2] + bo0) / (1.f + expf(-aI2));
                o.y = (dO[3] + bo1) / (1.f + expf(-aI3));
                *reinterpret_cast<float2*>(g_v + (size_t)n1*128 + c0) = o;
            }
        }
        __syncthreads();
    }
}

/* --------------------- K^T V partial (deterministic) ----------------- */
__global__ void kvred_k(){
    __shared__ float ks[32*64];
    __shared__ float vs[32*128];
    int b = blockIdx.y, ch = blockIdx.x;
    int tid = threadIdx.x, w = tid>>5, l = tid&31;

    float acc[8][4];
    #pragma unroll
    for (int r=0;r<8;r++){ acc[r][0]=0.f; acc[r][1]=0.f; acc[r][2]=0.f; acc[r][3]=0.f; }

    int nb0 = ch*CHSZ;
    for (int t0=0; t0<CHSZ; t0+=32){
        int nb = nb0 + t0;
        for (int t=tid; t<2048; t+=256){
            int nn = t>>6;
            ks[t] = (nb+nn < NN) ? g_k[((size_t)(b*NN+nb))*64 + t] : 0.f;
        }
        for (int t=tid; t<4096; t+=256){
            int nn = t>>7;
            vs[t] = (nb+nn < NN) ? g_v[((size_t)(b*NN+nb))*128 + t] : 0.f;
        }
        __syncthreads();
        for (int nn=0; nn<32; nn++){
            float4 vv = ((float4*)(vs + nn*128))[l];
            #pragma unroll
            for (int r=0;r<8;r++){
                float kv = ks[nn*64 + w*8 + r];
                acc[r][0] = fmaf(kv, vv.x, acc[r][0]);
                acc[r][1] = fmaf(kv, vv.y, acc[r][1]);
                acc[r][2] = fmaf(kv, vv.z, acc[r][2]);
                acc[r][3] = fmaf(kv, vv.w, acc[r][3]);
            }
        }
        __syncthreads();
    }
    size_t pb = (size_t)(b*CH+ch)*64 + w*8;
    #pragma unroll
    for (int r=0;r<8;r++){
        float4 o = make_float4(acc[r][0],acc[r][1],acc[r][2],acc[r][3]);
        ((float4*)g_part)[(pb+r)*32 + l] = o;
    }
}

__global__ void vred_k(){
    int idx = blockIdx.x*256 + threadIdx.x;
    int b = idx >> 13;
    int rem = idx & 8191;
    int m = rem >> 7, d = rem & 127;
    float s = 0.f;
    for (int ch=0; ch<CH; ch++)
        s += g_part[((size_t)(b*CH+ch)*64 + m)*128 + d];
    g_v2x[((size_t)b*64 + m)*128 + d] = s;
}

/* ------------- attention out + residual + layernorm ------------------ */
__global__ void attn_k(const float* __restrict__ res_in,
                       const float* __restrict__ lg, const float* __restrict__ lb){
    __shared__ float sv2x[64*128];
    __shared__ float sks[64];
    __shared__ float sg[128], sb[128];

    int b = blockIdx.y;
    int tid = threadIdx.x, w = tid>>5, l = tid&31;
    for (int t=tid; t<8192; t+=256) sv2x[t] = g_v2x[(size_t)b*8192 + t];
    if (tid<64)  sks[tid] = g_ksum[b*64 + tid];
    if (tid<128){ sg[tid] = lg[tid]; sb[tid] = lb[tid]; }
    __syncthreads();

    int nb0 = (blockIdx.x*8 + w)*8;
    float q0[8], q1[8];
    #pragma unroll
    for (int nd=0; nd<8; nd++){
        int n = nb0 + nd;
        if (n < NN){
            size_t i = (size_t)b*NN + n;
            q0[nd] = g_q[i*64 + l];
            q1[nd] = g_q[i*64 + 32 + l];
        } else { q0[nd] = 0.f; q1[nd] = 0.f; }
    }

    float4 acc[8]; float o2[8];
    #pragma unroll
    for (int nd=0; nd<8; nd++){ acc[nd]=make_float4(0.f,0.f,0.f,0.f); o2[nd]=0.f; }

    #pragma unroll 4
    for (int m=0; m<32; m++){
        float4 vx = ((float4*)(sv2x + m*128))[l];
        float km = sks[m];
        #pragma unroll
        for (int nd=0; nd<8; nd++){
            float qm = __shfl_sync(0xffffffffu, q0[nd], m);
            acc[nd].x = fmaf(qm, vx.x, acc[nd].x);
            acc[nd].y = fmaf(qm, vx.y, acc[nd].y);
            acc[nd].z = fmaf(qm, vx.z, acc[nd].z);
            acc[nd].w = fmaf(qm, vx.w, acc[nd].w);
            o2[nd]    = fmaf(qm, km, o2[nd]);
        }
    }
    #pragma unroll 4
    for (int m=0; m<32; m++){
        float4 vx = ((float4*)(sv2x + (m+32)*128))[l];
        float km = sks[m+32];
        #pragma unroll
        for (int nd=0; nd<8; nd++){
            float qm = __shfl_sync(0xffffffffu, q1[nd], m);
            acc[nd].x = fmaf(qm, vx.x, acc[nd].x);
            acc[nd].y = fmaf(qm, vx.y, acc[nd].y);
            acc[nd].z = fmaf(qm, vx.z, acc[nd].z);
            acc[nd].w = fmaf(qm, vx.w, acc[nd].w);
            o2[nd]    = fmaf(qm, km, o2[nd]);
        }
    }

    float4 g4 = ((float4*)sg)[l];
    float4 b4 = ((float4*)sb)[l];
    #pragma unroll 1
    for (int nd=0; nd<8; nd++){
        int n = nb0 + nd;
        if (n >= NN) continue;
        size_t i = (size_t)b*NN + n;
        float inv = 1.f / o2[nd];
        float4 res = ((const float4*)res_in)[i*32 + l];
        float4 t;
        t.x = fmaf(acc[nd].x, inv, res.x);
        t.y = fmaf(acc[nd].y, inv, res.y);
        t.z = fmaf(acc[nd].z, inv, res.z);
        t.w = fmaf(acc[nd].w, inv, res.w);
        float mu = warpSum(t.x+t.y+t.z+t.w) * (1.f/128.f);
        float dx=t.x-mu, dy=t.y-mu, dz=t.z-mu, dw=t.w-mu;
        float var = warpSum(dx*dx+dy*dy+dz*dz+dw*dw) * (1.f/128.f);
        float rs = rsqrtf(var + EPSLN);
        float4 o;
        o.x = dx*rs*g4.x + b4.x;
        o.y = dy*rs*g4.y + b4.y;
        o.z = dz*rs*g4.z + b4.z;
        o.w = dw*rs*g4.w + b4.w;
        ((float4*)g_h)[i*32 + l] = o;
    }
}

/* -------- relu(concat(h0,h)) @ W_reg.T + b_reg, transposed out ------- */
__global__ void final_k(const float* __restrict__ Wreg, const float* __restrict__ breg,
                        float* __restrict__ out)
{
    __shared__ float sWrT[256*12];
    __shared__ float sbr[12];
    int tid = threadIdx.x;
    for (int t=tid; t<3072; t+=256){ int to=t>>8, j=t&255; sWrT[j*12+to] = Wreg[t]; }
    if (tid<12) sbr[tid] = breg[tid];
    __syncthreads();

    int w = tid>>5, l = tid&31;
    int i = blockIdx.x*8 + w;
    int b = i / NN;
    int n = i - b*NN;
    size_t hb = (size_t)i*128;

    float acc[12];
    #pragma unroll
    for (int t=0;t<12;t++) acc[t]=0.f;

    #pragma unroll
    for (int c=0;c<8;c++){
        int j = c*32 + l;
        float vIn = (j < 128) ? g_h0[hb + j] : g_h[hb + j - 128];
        vIn = fmaxf(vIn, 0.f);
        #pragma unroll
        for (int t=0;t<12;t++) acc[t] = fmaf(vIn, sWrT[j*12+t], acc[t]);
    }
    #pragma unroll
    for (int t=0;t<12;t++) acc[t] = warpSum(acc[t]);
    if (l < 12) out[((size_t)b*12 + l)*NN + n] = acc[l] + sbr[l];
}

/* ------------------------------ launch ------------------------------- */
extern "C" void kernel_launch(void* const* d_in, const int* in_sizes, int n_in,
                              void* d_out, int out_size)
{
    const float* x        = (const float*)d_in[0];
    const float* node_emb = (const float*)d_in[1];
    const float* time_emb = (const float*)d_in[2];
    const float* week_emb = (const float*)d_in[3];
    const float* Win      = (const float*)d_in[4];
    const float* bin      = (const float*)d_in[5];
    const float* W1       = (const float*)d_in[6];
    const float* b1       = (const float*)d_in[7];
    const float* W2       = (const float*)d_in[8];
    const float* b2       = (const float*)d_in[9];
    const float* Wreg     = (const float*)d_in[10];
    const float* breg     = (const float*)d_in[11];
    const float* proj     = (const float*)d_in[12];

    cudaFuncSetAttribute(glu3_k, cudaFuncAttributeMaxDynamicSharedMemorySize, G3_TOT);

    float* g_h_ptr;  cudaGetSymbolAddress((void**)&g_h_ptr,  g_h);
    float* g_h0_ptr; cudaGetSymbolAddress((void**)&g_h0_ptr, g_h0);

    initmx_k<<<1,32>>>();
    phase1_k<<<NT/64,256>>>(x, node_emb, time_emb, week_emb,
                            Win, bin, W1, b1, W2, b2, proj);
    computek_k<<<(NT*64)/256,256>>>();
    ksump_k<<<dim3(CH,NB),256>>>();
    ksumr_k<<<1,256>>>();

    for (int layer=0; layer<2; layer++){
        const float* wi = (const float*)d_in[13 + layer*6 + 0];
        const float* bi = (const float*)d_in[13 + layer*6 + 1];
        const float* wo = (const float*)d_in[13 + layer*6 + 2];
        const float* bo = (const float*)d_in[13 + layer*6 + 3];
        const float* lg = (const float*)d_in[13 + layer*6 + 4];
        const float* lb = (const float*)d_in[13 + layer*6 + 5];

        const float* hin = (layer == 0) ? g_h0_ptr : g_h_ptr;

        glu3_k<<<148,512,G3_TOT>>>(hin, wi, bi, wo, bo);
        kvred_k<<<dim3(CH,NB),256>>>();
        vred_k<<<128,256>>>();
        attn_k<<<dim3((NN+63)/64,NB),256>>>(hin, lg, lb);
    }

    final_k<<<NT/8,256>>>(Wreg, breg, (float*)d_out);
}